// round 3
// baseline (speedup 1.0000x reference)
#include <cuda_runtime.h>
#include <cuda_bf16.h>

// Problem: out[g, :] = sum over rows r with batch[r]==g of x[r, :]
// (softmax over a size-1 axis == 1.0, so W and b are mathematically dead).
// x: [N, 128] fp32, batch: [N] int32 (SORTED; JAX x64-disabled downcasts the
// declared int64 to int32 — the harness only delivers fp32/int32/bf16),
// out: [10000, 128] fp32.
//
// Inputs are identified BY ELEMENT COUNT (robust to metadata ordering):
//   x     = unique largest input           (N*128 elems)
//   batch = unique input with N elements   (N = x_elems / 128)
//   W (128), b (1) are mathematically unused.
//
// Strategy: HBM-streaming. Each warp owns a contiguous chunk of 64 rows and
// all 128 columns (float4 per lane). Since batch is sorted, each warp's chunk
// spans ~1.64 segments on average: accumulate in registers, flush with a
// single red.global.add.v4.f32 per lane at each segment boundary.

#define C            128
#define TX           32          // lanes: 32 x float4 = 128 cols
#define TY           8           // warps per block
#define ROWS_PER_CHUNK 64        // contiguous rows per warp
#define ROWS_PER_BLOCK (TY * ROWS_PER_CHUNK)  // 512

__device__ __forceinline__ void red_add_v4(float* addr, float4 v) {
    asm volatile("red.global.add.v4.f32 [%0], {%1, %2, %3, %4};"
                 :: "l"(addr), "f"(v.x), "f"(v.y), "f"(v.z), "f"(v.w)
                 : "memory");
}

__global__ void zero_out_kernel(float* __restrict__ out, int n) {
    int i = blockIdx.x * blockDim.x + threadIdx.x;
    if (i < n) out[i] = 0.0f;
}

__global__ __launch_bounds__(TX * TY)
void segsum_kernel(const float4* __restrict__ x4,     // [N, 32] float4 view
                   const int* __restrict__ batch,     // [N] int32 sorted
                   float* __restrict__ out,           // [G, 128]
                   int N, int G) {
    const int tx = threadIdx.x;      // 0..31  -> column group (float4)
    const int ty = threadIdx.y;      // 0..7   -> warp / row chunk

    int r0 = blockIdx.x * ROWS_PER_BLOCK + ty * ROWS_PER_CHUNK;
    if (r0 >= N) return;
    int rend = r0 + ROWS_PER_CHUNK;
    if (rend > N) rend = N;

    float4 acc = make_float4(0.f, 0.f, 0.f, 0.f);
    int cur = __ldg(&batch[r0]);        // uniform across warp -> broadcast

    #pragma unroll 4
    for (int r = r0; r < rend; ++r) {
        int b = __ldg(&batch[r]);               // uniform broadcast load
        float4 v = __ldg(&x4[(size_t)r * (C / 4) + tx]);
        if (b != cur) {
            int g = min(max(cur, 0), G - 1);    // defensive clamp (no-op if sane)
            red_add_v4(out + (size_t)g * C + tx * 4, acc);
            acc = make_float4(0.f, 0.f, 0.f, 0.f);
            cur = b;
        }
        acc.x += v.x; acc.y += v.y; acc.z += v.z; acc.w += v.w;
    }
    int g = min(max(cur, 0), G - 1);
    red_add_v4(out + (size_t)g * C + tx * 4, acc);
}

extern "C" void kernel_launch(void* const* d_in, const int* in_sizes, int n_in,
                              void* d_out, int out_size) {
    // --- identify inputs by element count (robust to metadata ordering) ---
    int xi = 0;
    long long best = -1;
    for (int i = 0; i < n_in; ++i) {
        if ((long long)in_sizes[i] > best) { best = in_sizes[i]; xi = i; }
    }
    const int N = in_sizes[xi] / C;          // rows of x
    int bi = -1;
    for (int i = 0; i < n_in; ++i) {
        if (i != xi && in_sizes[i] == N) { bi = i; break; }
    }
    if (bi < 0) bi = (xi == 1) ? 0 : 1;      // fallback (shouldn't happen)

    const float* x     = (const float*)d_in[xi];   // [N,128] fp32
    const int*   batch = (const int*)d_in[bi];     // [N] int32 sorted
    float* out = (float*)d_out;
    const int G = out_size / C;

    // d_out is poisoned to 0xAA — zero it first (same stream, serialized).
    zero_out_kernel<<<(out_size + 255) / 256, 256>>>(out, out_size);

    dim3 block(TX, TY);
    int grid = (N + ROWS_PER_BLOCK - 1) / ROWS_PER_BLOCK;
    segsum_kernel<<<grid, block>>>((const float4*)x, batch, out, N, G);
}

// round 4
// speedup vs baseline: 1.0286x; 1.0286x over previous
#include <cuda_runtime.h>
#include <cuda_bf16.h>

// out[g, :] = sum over rows r with batch[r]==g of x[r, :]
// (softmax over a size-1 axis == 1.0 -> W, b mathematically dead).
// x: [N, 128] fp32, batch: [N] int32 SORTED, out: [10000, 128] fp32.
//
// Inputs identified BY ELEMENT COUNT (robust to metadata ordering):
//   x = unique largest (N*128), batch = unique with N elems.
//
// Tile strategy: each warp owns RPW contiguous rows. Per 32-row tile, ONE
// coalesced batch load; sorted => tile is single-segment iff first==last,
// giving a branch-free unroll-8 accumulate fast path (~73% of tiles).
// Segment boundaries flush register accumulators via red.global.add.v4.f32.

#define TX   32
#define TY   8
#define C    128
#define RPW  96                      // rows per warp (multiple of 32)
#define ROWS_PER_BLOCK (TY * RPW)    // 768

__device__ __forceinline__ void red_add_v4(float* addr, float4 v) {
    asm volatile("red.global.add.v4.f32 [%0], {%1, %2, %3, %4};"
                 :: "l"(addr), "f"(v.x), "f"(v.y), "f"(v.z), "f"(v.w)
                 : "memory");
}

__global__ void zero_out_kernel(float4* __restrict__ out, int n4) {
    int i = blockIdx.x * blockDim.x + threadIdx.x;
    if (i < n4) out[i] = make_float4(0.f, 0.f, 0.f, 0.f);
}

__global__ __launch_bounds__(TX * TY)
void segsum_kernel(const float4* __restrict__ x4,   // [N, 32] float4 view
                   const int* __restrict__ batch,   // [N] int32 sorted
                   float* __restrict__ out,         // [G, 128]
                   int N, int G) {
    const int lane = threadIdx.x;                   // column group
    int r0 = (blockIdx.x * TY + threadIdx.y) * RPW;
    if (r0 >= N) return;
    const int rend = min(r0 + RPW, N);

    float4 acc = make_float4(0.f, 0.f, 0.f, 0.f);
    int cur = __ldg(&batch[r0]);

    for (int t = r0; t < rend; t += 32) {
        const int m = rend - t < 32 ? rend - t : 32;
        // one coalesced id load per tile
        int id = __ldg(&batch[t + (lane < m ? lane : m - 1)]);
        const int first = __shfl_sync(0xffffffffu, id, 0);
        const int last  = __shfl_sync(0xffffffffu, id, 31);

        if (first == last && m == 32) {
            // tile entirely in one segment (sorted): branch-free fast path
            if (first != cur) {
                int g = min(max(cur, 0), G - 1);
                red_add_v4(out + (size_t)g * C + lane * 4, acc);
                acc = make_float4(0.f, 0.f, 0.f, 0.f);
                cur = first;
            }
            const float4* p = x4 + (size_t)t * (C / 4) + lane;
            #pragma unroll 8
            for (int i = 0; i < 32; ++i) {
                float4 v = __ldcs(p + (size_t)i * (C / 4));
                acc.x += v.x; acc.y += v.y; acc.z += v.z; acc.w += v.w;
            }
        } else {
            // boundary tile: per-row ids via shfl (no extra gmem traffic)
            for (int i = 0; i < m; ++i) {
                int b = __shfl_sync(0xffffffffu, id, i);
                float4 v = __ldcs(&x4[(size_t)(t + i) * (C / 4) + lane]);
                if (b != cur) {
                    int g = min(max(cur, 0), G - 1);
                    red_add_v4(out + (size_t)g * C + lane * 4, acc);
                    acc = make_float4(0.f, 0.f, 0.f, 0.f);
                    cur = b;
                }
                acc.x += v.x; acc.y += v.y; acc.z += v.z; acc.w += v.w;
            }
        }
    }
    int g = min(max(cur, 0), G - 1);
    red_add_v4(out + (size_t)g * C + lane * 4, acc);
}

extern "C" void kernel_launch(void* const* d_in, const int* in_sizes, int n_in,
                              void* d_out, int out_size) {
    // identify inputs by element count
    int xi = 0;
    long long best = -1;
    for (int i = 0; i < n_in; ++i)
        if ((long long)in_sizes[i] > best) { best = in_sizes[i]; xi = i; }
    const int N = in_sizes[xi] / C;
    int bi = -1;
    for (int i = 0; i < n_in; ++i)
        if (i != xi && in_sizes[i] == N) { bi = i; break; }
    if (bi < 0) bi = (xi == 1) ? 0 : 1;

    const float* x     = (const float*)d_in[xi];
    const int*   batch = (const int*)d_in[bi];
    float* out = (float*)d_out;
    const int G = out_size / C;

    // zero the poisoned output (vectorized)
    int n4 = out_size / 4;
    zero_out_kernel<<<(n4 + 255) / 256, 256>>>((float4*)out, n4);

    dim3 block(TX, TY);
    int grid = (N + ROWS_PER_BLOCK - 1) / ROWS_PER_BLOCK;
    segsum_kernel<<<grid, block>>>((const float4*)x, batch, out, N, G);
}